// round 15
// baseline (speedup 1.0000x reference)
#include <cuda_runtime.h>
#include <cuda_bf16.h>
#include <stdint.h>

#define B_ 128
#define T_ 1024
#define I_ 64
#define W_ 32
#define H_ 256
#define BT_ (B_*T_)

typedef unsigned long long u64;

// ---------------- scratch (__device__ globals are allowed) ------------------
__device__ float g_pre_ho[(size_t)BT_*H_];   // [T][B][H]
__device__ float g_pre_i [(size_t)BT_*H_];
__device__ float g_pre_g [(size_t)BT_*H_];
__device__ float g_pre_f [(size_t)BT_*H_];
__device__ float g_pre_o [(size_t)BT_*H_];
__device__ int   g_done  [T_];               // 2 tiles per t

__device__ __forceinline__ float sigm(float x) { return 1.f / (1.f + __expf(-x)); }
__device__ __forceinline__ float tanh_f(float x) {
    float e = __expf(2.f * x);
    return 1.f - __fdividef(2.f, e + 1.f);
}

// packed f32x2 FMA (sm_100+)
__device__ __forceinline__ u64 fma2(u64 a, u64 b, u64 c) {
    u64 d;
    asm("fma.rn.f32x2 %0, %1, %2, %3;" : "=l"(d) : "l"(a), "l"(b), "l"(c));
    return d;
}
__device__ __forceinline__ float red2(u64 v) {
    float x, y;
    asm("mov.b64 {%0, %1}, %2;" : "=f"(x), "=f"(y) : "l"(v));
    return x + y;
}

__device__ __forceinline__ uint32_t smem_u32(const void* p) {
    uint32_t a;
    asm("{ .reg .u64 t; cvta.to.shared.u64 t, %1; cvt.u32.u64 %0, t; }" : "=r"(a) : "l"(p));
    return a;
}
#define CLUSTER_SYNC() do { \
    asm volatile("barrier.cluster.arrive.aligned;" ::: "memory"); \
    asm volatile("barrier.cluster.wait.aligned;"   ::: "memory"); \
} while (0)

// remote DSMEM store fused with tx-signal on dest CTA's mbarrier
__device__ __forceinline__ void st_async_f32(uint32_t raddr, float v, uint32_t rmbar) {
    asm volatile(
        "st.async.shared::cluster.mbarrier::complete_tx::bytes.f32 [%0], %1, [%2];"
        :: "r"(raddr), "f"(v), "r"(rmbar) : "memory");
}
__device__ __forceinline__ void mb_init(uint32_t mbar, uint32_t cnt) {
    asm volatile("mbarrier.init.shared.b64 [%0], %1;" :: "r"(mbar), "r"(cnt) : "memory");
}
__device__ __forceinline__ void mb_expect_tx(uint32_t mbar, uint32_t bytes) {
    asm volatile("mbarrier.arrive.expect_tx.shared.b64 _, [%0], %1;"
                 :: "r"(mbar), "r"(bytes) : "memory");
}
__device__ __forceinline__ void mb_wait(uint32_t mbar, uint32_t parity) {
    uint32_t done;
    asm volatile(
        "{\n\t.reg .pred p;\n\t"
        "mbarrier.try_wait.parity.acquire.cluster.shared::cta.b64 p, [%1], %2;\n\t"
        "selp.b32 %0, 1, 0, p;\n\t}"
        : "=r"(done) : "r"(mbar), "r"(parity) : "memory");
    if (!done) {
        asm volatile(
            "{\n\t.reg .pred P1;\n\t"
            "WL_%=:\n\t"
            "mbarrier.try_wait.parity.acquire.cluster.shared::cta.b64 P1, [%0], %1, 0x989680;\n\t"
            "@P1 bra.uni WD_%=;\n\t"
            "bra.uni WL_%=;\n\t"
            "WD_%=:\n\t}"
            :: "r"(mbar), "r"(parity) : "memory");
    }
}

__device__ __forceinline__ void wait_done2(int t) {
    volatile int* p = &g_done[t];
    while (*p < 2) { __nanosleep(200); }
}

// ===================== zero kernel (reset flags each replay) ================
__global__ void k_zero() {
    int i = blockIdx.x * blockDim.x + threadIdx.x;
    if (i < T_) g_done[i] = 0;
}

// ===================== fused kernel: SMEM layout (floats) ===================
// Recurrence (blocks 0..63): R13 layout
#define RH_F     2048
#define OFF_WT   0
#define OFF_WI   8320
#define OFF_WG   16640
#define OFF_WF   24960
#define OFF_WO   33280
#define OFF_HNA  41600
#define OFF_HOA  43648
#define OFF_HNB  45696
#define OFF_HOB  47744
#define OFF_PP   49792
#define OFF_MB   57984
#define REC_SMEM_FLOATS 57992
#define REC_SMEM_BYTES  (REC_SMEM_FLOATS*4)
#define D_HOA    8192
#define D_HNB    16384
#define D_HOB    24576
#define PHASE_TX 8192u
// Producer (blocks 64..127): panels of 32*66 float2 = 4224 floats
#define P_A2X    0
#define P_A2S    4224       // 3 panels: 4224..16895
#define P_B2     16896
#define P_ECH    21120      // 4 chunks x 4224
#define P_XW     38016      // 64 x 36 floats

// ---------------- producer helpers -----------------------------------------
__device__ __forceinline__ void stage512(float2* S, const float4* rowptr, int r, int q) {
#pragma unroll
    for (int u = 0; u < 2; ++u) {
        float4 v = rowptr[q + 8*u];
        int k2 = 2*(q + 8*u);
        S[k2*66 + r]     = make_float2(v.x, v.y);
        S[(k2+1)*66 + r] = make_float2(v.z, v.w);
    }
}
__device__ __forceinline__ void zero512(float2* S, int r, int q) {
#pragma unroll
    for (int u = 0; u < 2; ++u) {
        int k2 = 2*(q + 8*u);
        S[k2*66 + r]     = make_float2(0.f, 0.f);
        S[(k2+1)*66 + r] = make_float2(0.f, 0.f);
    }
}
__device__ __forceinline__ void accum512(const float2* A2, const float2* B2,
                                         int tx, int ty, u64 acc[2][4]) {
#pragma unroll 8
    for (int k2 = 0; k2 < 32; ++k2) {
        u64 a0 = *(const u64*)(A2 + k2*66 + ty*2);
        u64 a1 = *(const u64*)(A2 + k2*66 + ty*2 + 1);
        ulonglong2 bL = *(const ulonglong2*)(B2 + k2*66 + tx*4);
        ulonglong2 bH = *(const ulonglong2*)(B2 + k2*66 + tx*4 + 2);
        u64 bv[4] = {bL.x, bL.y, bH.x, bH.y};
#pragma unroll
        for (int jj = 0; jj < 4; ++jj) {
            acc[0][jj] = fma2(a0, bv[jj], acc[0][jj]);
            acc[1][jj] = fma2(a1, bv[jj], acc[1][jj]);
        }
    }
}
__device__ __forceinline__ void writeout2(float* dst, size_t m, int col,
                                          u64 acc[2][4], float4 bv) {
    *(float4*)&dst[m*H_ + col] =
        make_float4(red2(acc[0][0])+bv.x, red2(acc[0][1])+bv.y,
                    red2(acc[0][2])+bv.z, red2(acc[0][3])+bv.w);
    *(float4*)&dst[(m+1)*H_ + col] =
        make_float4(red2(acc[1][0])+bv.x, red2(acc[1][1])+bv.y,
                    red2(acc[1][2])+bv.z, red2(acc[1][3])+bv.w);
}

// ---------------- producer path ---------------------------------------------
__device__ void producer_main(float* smf, int pidx,
    const float* x, const float* xw,
    const float* w_e, const float* b_e,
    const float* w_ix, const float* w_fx, const float* w_ox, const float* w_gx,
    const float* w_ie, const float* w_fe, const float* w_oe,
    const float* b_i, const float* b_f, const float* b_o, const float* b_g,
    const float* w_d, const float* w_w, const float* w_m)
{
    int tid = threadIdx.x;
    float2* A2X = (float2*)(smf + P_A2X);
    float2* B2  = (float2*)(smf + P_B2);
    int r8 = tid >> 3, q8 = tid & 7;     // staging coords
    int tx = tid & 15, ty = tid >> 4;    // gemm coords (ty 0..31 -> 2 rows)
    int half = tid >> 8, colE = tid & 255;

    // w_e row for this thread's e-column (reused every tile)
    float4 wr[8];
    {
        const float4* wp = (const float4*)(w_e + (size_t)colE*W_);
#pragma unroll
        for (int u = 0; u < 8; ++u) wr[u] = wp[u];
    }
    float ebias = b_e[colE];
    int ekc = colE >> 6, ec = colE & 63;
    int ek2 = ec >> 1, elan = ec & 1;

    for (int tt = pidx; tt < 2*T_; tt += 64) {
        int t = tt >> 1, mb = tt & 1;
        int b0 = mb*64 + r8;

        // ---- stage xw rows [64][32] -> P_XW (stride 36) ----
        {
            int rr = tid >> 3, qq = tid & 7;
            float4 v = *(const float4*)(xw + ((size_t)(mb*64+rr)*T_ + t)*W_ + qq*4);
            *(float4*)(smf + P_XW + rr*36 + qq*4) = v;
        }
        // ---- stage A2X and 3 shifted panels ----
        stage512(A2X, (const float4*)(x + ((size_t)b0*T_ + t)*I_), r8, q8);
        {
            const int SH[3] = {1, 7, 30};
#pragma unroll
            for (int s = 0; s < 3; ++s) {
                int bs = b0 - SH[s];
                float2* P = (float2*)(smf + P_A2S + s*4224);
                if (bs >= 0)
                    stage512(P, (const float4*)(x + ((size_t)bs*T_ + t)*I_), r8, q8);
                else
                    zero512(P, r8, q8);
            }
        }
        __syncthreads();
        // ---- e tile: e[r][colE] for r = half*32 .. half*32+31 ----
        {
            float* ebase = smf + P_ECH + ekc*4224;
            const float* xwrow = smf + P_XW + (half*32)*36;
#pragma unroll 4
            for (int rr = 0; rr < 32; ++rr) {
                const float* xr = xwrow + rr*36;
                float acc = ebias;
#pragma unroll
                for (int u = 0; u < 8; ++u)
                    acc += wr[u].x*xr[4*u] + wr[u].y*xr[4*u+1]
                         + wr[u].z*xr[4*u+2] + wr[u].w*xr[4*u+3];
                ebase[(ek2*66 + half*32 + rr)*2 + elan] = sigm(acc);
            }
        }
        __syncthreads();

        // ---- GEMMs: 4 col-chunks x (4 gates + ho) ----
        size_t mrow = (size_t)t*B_ + mb*64 + ty*2;
        for (int cc = 0; cc < 4; ++cc) {
            int col0 = cc*64;
            for (int gate = 0; gate < 4; ++gate) {
                const float* wx = gate==0?w_ix:gate==1?w_fx:gate==2?w_ox:w_gx;
                u64 acc[2][4] = {};
                __syncthreads();
                stage512(B2, (const float4*)(wx + (size_t)(col0+r8)*I_), r8, q8);
                __syncthreads();
                accum512(A2X, B2, tx, ty, acc);
                if (gate < 3) {
                    const float* we = gate==0?w_ie:gate==1?w_fe:w_oe;
                    for (int kc = 0; kc < 4; ++kc) {
                        __syncthreads();
                        stage512(B2, (const float4*)(we + (size_t)(col0+r8)*H_ + kc*64), r8, q8);
                        __syncthreads();
                        accum512((const float2*)(smf + P_ECH + kc*4224), B2, tx, ty, acc);
                    }
                }
                const float* bias = gate==0?b_i:gate==1?b_f:gate==2?b_o:b_g;
                float* dst = gate==0?g_pre_i:gate==1?g_pre_f:gate==2?g_pre_o:g_pre_g;
                float4 bv = *(const float4*)&bias[col0 + tx*4];
                writeout2(dst, mrow, col0 + tx*4, acc, bv);
            }
            {
                u64 acc[2][4] = {};
                const float* WS0 = w_d;
                const float* WS1 = w_w;
                const float* WS2 = w_m;
#pragma unroll
                for (int s = 0; s < 3; ++s) {
                    const float* ws = s==0?WS0:s==1?WS1:WS2;
                    __syncthreads();
                    stage512(B2, (const float4*)(ws + (size_t)(col0+r8)*I_), r8, q8);
                    __syncthreads();
                    accum512((const float2*)(smf + P_A2S + s*4224), B2, tx, ty, acc);
                }
                float4 bv = *(const float4*)&b_e[col0 + tx*4];
                writeout2(g_pre_ho, mrow, col0 + tx*4, acc, bv);
            }
        }
        __syncthreads();
        __threadfence();
        if (tid == 0) atomicAdd(&g_done[t], 1);
        __syncthreads();
    }
}

// ---------------- recurrence helpers (R13 winner, unchanged) ----------------
__device__ __forceinline__ void rec_phase1(const float* wt_s, const float* hn,
                                           float* pp1, int warp, int colA, int k1)
{
    u64 A1[8] = {};
#pragma unroll
    for (int kb = 0; kb < 16; kb += 4) {
        int k = k1 + kb;
        ulonglong2 wv = *(const ulonglong2*)&wt_s[colA*260 + k];
        ulonglong2 hv[8];
#pragma unroll
        for (int r = 0; r < 8; ++r) hv[r] = *(const ulonglong2*)&hn[r*256 + k];
#pragma unroll
        for (int r = 0; r < 8; ++r) {
            A1[r] = fma2(wv.x, hv[r].x, A1[r]);
            A1[r] = fma2(wv.y, hv[r].y, A1[r]);
        }
    }
#pragma unroll
    for (int r = 0; r < 8; ++r) pp1[(r*16 + warp)*32 + colA] = red2(A1[r]);
}

__device__ __forceinline__ void rec_phase2(const float* wA_s, const float* wB_s,
                                           const float* ho, float2* ppX,
                                           int q8, int colA, int k2b)
{
    u64 Aa[8] = {}, Ab[8] = {};
#pragma unroll
    for (int kb = 0; kb < 32; kb += 4) {
        int k = k2b + kb;
        ulonglong2 hv[8];
#pragma unroll
        for (int r = 0; r < 8; ++r) hv[r] = *(const ulonglong2*)&ho[r*256 + k];
        ulonglong2 wa = *(const ulonglong2*)&wA_s[colA*260 + k];
        ulonglong2 wb = *(const ulonglong2*)&wB_s[colA*260 + k];
#pragma unroll
        for (int r = 0; r < 8; ++r) {
            Aa[r] = fma2(wa.x, hv[r].x, Aa[r]);
            Aa[r] = fma2(wa.y, hv[r].y, Aa[r]);
            Ab[r] = fma2(wb.x, hv[r].x, Ab[r]);
            Ab[r] = fma2(wb.y, hv[r].y, Ab[r]);
        }
    }
#pragma unroll
    for (int r = 0; r < 8; ++r)
        ppX[(r*8 + q8)*32 + colA] = make_float2(red2(Aa[r]), red2(Ab[r]));
}

// ======================= fused kernel =======================================
__global__ void __cluster_dims__(8,1,1) __launch_bounds__(512,1)
k_fused(const float* __restrict__ x,    const float* __restrict__ xw,
        const float* __restrict__ w_e,  const float* __restrict__ b_e,
        const float* __restrict__ w_ix, const float* __restrict__ w_fx,
        const float* __restrict__ w_ox, const float* __restrict__ w_gx,
        const float* __restrict__ w_ie, const float* __restrict__ w_fe,
        const float* __restrict__ w_oe,
        const float* __restrict__ b_i,  const float* __restrict__ b_f,
        const float* __restrict__ b_o,  const float* __restrict__ b_g,
        const float* __restrict__ w_d,  const float* __restrict__ w_w,
        const float* __restrict__ w_m,
        const float* __restrict__ w_t,  const float* __restrict__ w_ih,
        const float* __restrict__ w_gh, const float* __restrict__ w_fo,
        const float* __restrict__ w_oh, float* __restrict__ out)
{
    extern __shared__ float sm[];

    if (blockIdx.x >= 64) {
        producer_main(sm, (int)blockIdx.x - 64,
                      x, xw, w_e, b_e, w_ix, w_fx, w_ox, w_gx,
                      w_ie, w_fe, w_oe, b_i, b_f, b_o, b_g, w_d, w_w, w_m);
        return;
    }

    // -------- recurrence (8 clusters x 8 CTAs; R13 logic + flag waits) ------
    float*  wt_s  = sm + OFF_WT;
    float*  wi_s  = sm + OFF_WI;
    float*  wg_s  = sm + OFF_WG;
    float*  wf_s  = sm + OFF_WF;
    float*  wo_s  = sm + OFF_WO;
    float*  hnA_s = sm + OFF_HNA;
    float*  hoA_s = sm + OFF_HOA;
    float*  hnB_s = sm + OFF_HNB;
    float*  hoB_s = sm + OFF_HOB;
    float*  pp1   = sm + OFF_PP;
    float2* pp_ig = (float2*)(sm + OFF_PP);
    float2* pp_fo = (float2*)(sm + OFF_PP + 4096);

    int tid = threadIdx.x;
    int lane = tid & 31, warp = tid >> 5;
    int j = blockIdx.x & 7;
    int g = blockIdx.x >> 3;

    uint32_t mbL = smem_u32(&sm[OFF_MB]);
    uint32_t mbL_hnA = mbL, mbL_hoA = mbL + 8, mbL_hnB = mbL + 16, mbL_hoB = mbL + 24;

    for (int idx = tid; idx < 32*64; idx += 512) {
        int col = idx >> 6, kq = idx & 63;
        *(float4*)&wt_s[col*260 + kq*4] =
            *(const float4*)(w_t + (size_t)(j*32+col)*H_ + kq*4);
    }
    for (int idx = tid; idx < 4*32*64; idx += 512) {
        int gg = idx >> 11, col = (idx >> 6) & 31, kq = idx & 63;
        const float* W = (gg==0)?w_ih:(gg==1)?w_gh:(gg==2)?w_fo:w_oh;
        float* S = (gg==0)?wi_s:(gg==1)?wg_s:(gg==2)?wf_s:wo_s;
        *(float4*)&S[col*260 + kq*4] =
            *(const float4*)(W + (size_t)(j*32+col)*H_ + kq*4);
    }
    for (int idx = tid; idx < 4*RH_F; idx += 512) hnA_s[idx] = 0.f;
    if (tid == 0) {
        mb_init(mbL_hnA, 1); mb_init(mbL_hoA, 1);
        mb_init(mbL_hnB, 1); mb_init(mbL_hoB, 1);
        mb_expect_tx(mbL_hnA, PHASE_TX);
        mb_expect_tx(mbL_hoA, PHASE_TX);
        mb_expect_tx(mbL_hnB, PHASE_TX);
        mb_expect_tx(mbL_hoB, PHASE_TX);
    }
    __syncthreads();
    CLUSTER_SYNC();

    int colA = lane;
    int q8 = warp & 7, gp = warp >> 3;
    int k1 = warp * 16;
    int k2b = q8 * 32;
    const float* wA_s = gp ? wf_s : wi_s;
    const float* wB_s = gp ? wo_s : wg_s;
    float2* ppX = gp ? pp_fo : pp_ig;

    bool fin = (tid < 256);
    int rowR = tid >> 5, colR = lane;
    int cg    = j*32 + colR;
    int browA = g*16 + rowR;
    int browB = browA + 8;
    float cA = 0.f, cB = 0.f;

    uint32_t hnA_rem[8], mb_rem[8];
    if (fin) {
        uint32_t hnA_loc = smem_u32(&hnA_s[rowR*256 + cg]);
#pragma unroll
        for (int p = 0; p < 8; ++p) {
            asm("mapa.shared::cluster.u32 %0, %1, %2;"
                : "=r"(hnA_rem[p]) : "r"(hnA_loc), "r"(p));
            asm("mapa.shared::cluster.u32 %0, %1, %2;"
                : "=r"(mb_rem[p]) : "r"(mbL), "r"(p));
        }
#pragma unroll
        for (int p = 0; p < 8; ++p)
            st_async_f32(hnA_rem[p] + D_HNB, 0.f, mb_rem[p] + 16);
    }

    // wait for pre[t=0] then preload
    if (tid == 0) { wait_done2(0); __threadfence(); }
    __syncthreads();
    float phoA=0, piA=0, pgA=0, pfA=0, poA=0;
    float phoB=0, piB=0, pgB=0, pfB=0, poB=0;
    if (fin) {
        size_t pa = (size_t)browA*H_ + cg;
        size_t pb = (size_t)browB*H_ + cg;
        phoA=g_pre_ho[pa]; piA=g_pre_i[pa]; pgA=g_pre_g[pa]; pfA=g_pre_f[pa]; poA=g_pre_o[pa];
        phoB=g_pre_ho[pb]; piB=g_pre_i[pb]; pgB=g_pre_g[pb]; pfB=g_pre_f[pb]; poB=g_pre_o[pb];
    }

    for (int t = 0; t < T_; ++t) {
        uint32_t par = (uint32_t)(t & 1);

        // ---- P1A ----
        rec_phase1(wt_s, hnA_s, pp1, warp, colA, k1);
        __syncthreads();
        if (fin) {
            float s1 = phoA;
#pragma unroll
            for (int qq = 0; qq < 16; ++qq) s1 += pp1[(rowR*16 + qq)*32 + colR];
            float hov = sigm(s1);
#pragma unroll
            for (int p = 0; p < 8; ++p)
                st_async_f32(hnA_rem[p] + D_HOA, hov, mb_rem[p] + 8);
        }
        __syncthreads();
        mb_wait(mbL_hnB, par);
        if (tid == 0) mb_expect_tx(mbL_hnB, PHASE_TX);

        // ---- P1B ----  (early probe of done[t+1]; latency hidden by compute)
        int dv = 2;
        if (tid == 0 && t+1 < T_) dv = *(volatile int*)&g_done[t+1];
        rec_phase1(wt_s, hnB_s, pp1, warp, colA, k1);
        if (tid == 0) {
            if (t+1 < T_ && dv < 2) wait_done2(t+1);
            __threadfence();
        }
        __syncthreads();
        if (fin) {
            float s1 = phoB;
#pragma unroll
            for (int qq = 0; qq < 16; ++qq) s1 += pp1[(rowR*16 + qq)*32 + colR];
            float hov = sigm(s1);
#pragma unroll
            for (int p = 0; p < 8; ++p)
                st_async_f32(hnA_rem[p] + D_HOB, hov, mb_rem[p] + 24);
        }
        float nphoA=phoA, npiA=piA, npgA=pgA, npfA=pfA, npoA=poA;
        float nphoB=phoB, npiB=piB, npgB=pgB, npfB=pfB, npoB=poB;
        if (fin) {
            int tn = (t+1 < T_) ? t+1 : t;
            size_t pa = ((size_t)tn*B_ + browA)*H_ + cg;
            size_t pb = ((size_t)tn*B_ + browB)*H_ + cg;
            nphoA=g_pre_ho[pa]; npiA=g_pre_i[pa]; npgA=g_pre_g[pa]; npfA=g_pre_f[pa]; npoA=g_pre_o[pa];
            nphoB=g_pre_ho[pb]; npiB=g_pre_i[pb]; npgB=g_pre_g[pb]; npfB=g_pre_f[pb]; npoB=g_pre_o[pb];
        }
        __syncthreads();
        mb_wait(mbL_hoA, par);
        if (tid == 0) mb_expect_tx(mbL_hoA, PHASE_TX);

        // ---- P2A ----
        rec_phase2(wA_s, wB_s, hoA_s, ppX, q8, colA, k2b);
        __syncthreads();
        if (fin) {
            float si = piA, sg = pgA, sf = pfA, so = poA;
#pragma unroll
            for (int qq = 0; qq < 8; ++qq) {
                float2 vig = pp_ig[(rowR*8 + qq)*32 + colR];
                float2 vfo = pp_fo[(rowR*8 + qq)*32 + colR];
                si += vig.x; sg += vig.y; sf += vfo.x; so += vfo.y;
            }
            float iv = sigm(si), gv = tanh_f(sg), fv = sigm(sf), ov = sigm(so);
            cA = fv*cA + iv*gv;
            float hnv = ov * tanh_f(cA);
#pragma unroll
            for (int p = 0; p < 8; ++p)
                st_async_f32(hnA_rem[p], hnv, mb_rem[p]);
            size_t ob = ((size_t)browA*T_ + t)*H_ + cg;
            out[ob] = hnv;
            out[(size_t)BT_*H_ + ob] = cA;
        }
        __syncthreads();
        mb_wait(mbL_hoB, par);
        if (tid == 0) mb_expect_tx(mbL_hoB, PHASE_TX);

        // ---- P2B ----
        rec_phase2(wA_s, wB_s, hoB_s, ppX, q8, colA, k2b);
        __syncthreads();
        if (fin) {
            float si = piB, sg = pgB, sf = pfB, so = poB;
#pragma unroll
            for (int qq = 0; qq < 8; ++qq) {
                float2 vig = pp_ig[(rowR*8 + qq)*32 + colR];
                float2 vfo = pp_fo[(rowR*8 + qq)*32 + colR];
                si += vig.x; sg += vig.y; sf += vfo.x; so += vfo.y;
            }
            float iv = sigm(si), gv = tanh_f(sg), fv = sigm(sf), ov = sigm(so);
            cB = fv*cB + iv*gv;
            float hnv = ov * tanh_f(cB);
#pragma unroll
            for (int p = 0; p < 8; ++p)
                st_async_f32(hnA_rem[p] + D_HNB, hnv, mb_rem[p] + 16);
            size_t ob = ((size_t)browB*T_ + t)*H_ + cg;
            out[ob] = hnv;
            out[(size_t)BT_*H_ + ob] = cB;
            phoA=nphoA; piA=npiA; pgA=npgA; pfA=npfA; poA=npoA;
            phoB=nphoB; piB=npiB; pgB=npgB; pfB=npfB; poB=npoB;
        }
        __syncthreads();
        mb_wait(mbL_hnA, par);
        if (tid == 0) mb_expect_tx(mbL_hnA, PHASE_TX);
    }
    mb_wait(mbL_hnB, 0);
    CLUSTER_SYNC();
}

// ============================== launch ======================================
extern "C" void kernel_launch(void* const* d_in, const int* in_sizes, int n_in,
                              void* d_out, int out_size)
{
    const float* x    = (const float*)d_in[0];
    const float* xw   = (const float*)d_in[1];
    const float* w_ix = (const float*)d_in[2];
    const float* w_ih = (const float*)d_in[3];
    const float* w_ie = (const float*)d_in[4];
    const float* b_i  = (const float*)d_in[5];
    const float* w_fx = (const float*)d_in[6];
    const float* w_fo = (const float*)d_in[7];
    const float* w_fe = (const float*)d_in[8];
    const float* b_f  = (const float*)d_in[9];
    const float* w_ox = (const float*)d_in[10];
    const float* w_oh = (const float*)d_in[11];
    const float* w_oe = (const float*)d_in[12];
    const float* b_o  = (const float*)d_in[13];
    const float* w_gx = (const float*)d_in[14];
    const float* w_gh = (const float*)d_in[15];
    const float* b_g  = (const float*)d_in[16];
    const float* w_d  = (const float*)d_in[17];
    const float* w_w  = (const float*)d_in[18];
    const float* w_m  = (const float*)d_in[19];
    const float* w_t  = (const float*)d_in[20];
    const float* w_e  = (const float*)d_in[21];
    const float* b_e  = (const float*)d_in[22];
    float* out = (float*)d_out;

    static int smem_set = 0;
    if (!smem_set) {
        cudaFuncSetAttribute(k_fused, cudaFuncAttributeMaxDynamicSharedMemorySize,
                             REC_SMEM_BYTES);
        smem_set = 1;
    }
    k_zero<<<1, 1024>>>();
    k_fused<<<128, 512, REC_SMEM_BYTES>>>(
        x, xw, w_e, b_e, w_ix, w_fx, w_ox, w_gx, w_ie, w_fe, w_oe,
        b_i, b_f, b_o, b_g, w_d, w_w, w_m,
        w_t, w_ih, w_gh, w_fo, w_oh, out);
}